// round 16
// baseline (speedup 1.0000x reference)
#include <cuda_runtime.h>
#include <cstdint>

// out[m,n] = a * (h[m,:] @ B2[:,n]) + (1-a) * h[m,n]
// B2[k, head*64+d] = W[head,k,d]; a = clip(res_alpha,0,1).
// (softmax row-sums are exactly 1 -> attention block is identity; adj unused)
//
// bf16 2-split x 3-term emulated-fp32 GEMM on mma.m16n8k16:
//   x = hi + lo (hi = fp32 truncated to bf16), D = Ahi*Bhi + Ahi*Blo + Alo*Bhi
// R13 = R12 with the N-halves MERGED: each term is issued across all 16
// independent acc tiles before any acc is reused (reuse distance 8 -> 16,
// ~105 cyc at rt 6.6 — covers fallback-HMMA accumulator latency).
// Fragment loads stay demand-ordered between terms (Bl under t1, Al under t2).

#define K_DIM   256
#define NDIM    256
#define BM      128
#define BN      128
#define KC      32
#define NCHUNK  (K_DIM / KC)
#define RSTRIDE 80                       // bytes per smem row (64 data + 16 pad)
#define PLANE   (128 * RSTRIDE)          // 10240 B per plane (128 rows)
#define STAGE_B (4 * PLANE)              // Ahi, Alo, Bhi, Blo = 40960 B
#define THREADS 256

__device__ uint32_t g_Bh[NDIM * K_DIM / 2];   // [n][pair] bf16x2 hi
__device__ uint32_t g_Bl[NDIM * K_DIM / 2];

__device__ __forceinline__ void split_pack(float f0, float f1,
                                           uint32_t& hi, uint32_t& lo) {
    uint32_t u0 = __float_as_uint(f0);
    uint32_t u1 = __float_as_uint(f1);
    hi = __byte_perm(u0, u1, 0x7632);
    float r0 = f0 - __uint_as_float(u0 & 0xFFFF0000u);
    float r1 = f1 - __uint_as_float(u1 & 0xFFFF0000u);
    lo = __byte_perm(__float_as_uint(r0), __float_as_uint(r1), 0x7632);
}

__global__ void prep_Bt(const float* __restrict__ W) {
    int idx = blockIdx.x * blockDim.x + threadIdx.x;   // 32768
    int n = idx >> 7;
    int p = idx & 127;
    int head = n >> 6, d = n & 63;
    float f0 = W[((size_t)head * K_DIM + 2 * p) * 64 + d];
    float f1 = W[((size_t)head * K_DIM + 2 * p + 1) * 64 + d];
    uint32_t hi, lo;
    split_pack(f0, f1, hi, lo);
    g_Bh[n * 128 + p] = hi;
    g_Bl[n * 128 + p] = lo;
}

__device__ __forceinline__ void mma_bf16(float d[4],
                                         uint32_t a0, uint32_t a1, uint32_t a2, uint32_t a3,
                                         uint32_t b0, uint32_t b1) {
    asm volatile(
        "mma.sync.aligned.m16n8k16.row.col.f32.bf16.bf16.f32 "
        "{%0,%1,%2,%3}, {%4,%5,%6,%7}, {%8,%9}, {%0,%1,%2,%3};"
        : "+f"(d[0]), "+f"(d[1]), "+f"(d[2]), "+f"(d[3])
        : "r"(a0), "r"(a1), "r"(a2), "r"(a3), "r"(b0), "r"(b1));
}
__device__ __forceinline__ uint4 ldsm4(uint32_t saddr) {
    uint4 v;
    asm volatile("ldmatrix.sync.aligned.m8n8.x4.shared.b16 {%0,%1,%2,%3}, [%4];"
                 : "=r"(v.x), "=r"(v.y), "=r"(v.z), "=r"(v.w) : "r"(saddr));
    return v;
}
__device__ __forceinline__ void cp16(uint32_t saddr, const void* g) {
    asm volatile("cp.async.cg.shared.global [%0], [%1], 16;"
                 :: "r"(saddr), "l"(g) : "memory");
}
__device__ __forceinline__ void sts128(uint32_t saddr, uint32_t x, uint32_t y,
                                       uint32_t z, uint32_t w) {
    asm volatile("st.shared.v4.u32 [%0], {%1,%2,%3,%4};"
                 :: "r"(saddr), "r"(x), "r"(y), "r"(z), "r"(w) : "memory");
}

__global__ __launch_bounds__(THREADS, 2)
void gat_mma_gemm(const float* __restrict__ h,
                  const float* __restrict__ res_alpha,
                  float* __restrict__ out)
{
    extern __shared__ uint32_t su[];
    const uint32_t smem_b = (uint32_t)__cvta_generic_to_shared(su);

    const int tid = threadIdx.x;
    const int wid = tid >> 5;
    const int lid = tid & 31;
    const int grp = lid >> 2;
    const int tig = lid & 3;

    const int m0 = blockIdx.y * BM;
    const int n0 = blockIdx.x * BN;
    const int wm = (wid & 3) * 32;
    const int wn = (wid >> 2) * 64;

    const uint32_t a_lane = (uint32_t)((wm + (lid & 15)) * RSTRIDE + ((lid >> 4) & 1) * 16);
    const uint32_t b_lane = (uint32_t)((wn + (lid & 7) + ((lid >> 4) & 1) * 8) * RSTRIDE +
                                      ((lid >> 3) & 1) * 16);

    const int ld_row = tid >> 1;
    const int ld_kh  = tid & 1;

    float acc[2][8][4];
    #pragma unroll
    for (int mt = 0; mt < 2; ++mt)
        #pragma unroll
        for (int nt = 0; nt < 8; ++nt)
            #pragma unroll
            for (int q = 0; q < 4; ++q)
                acc[mt][nt][q] = 0.0f;

    float4 pf[4];

    auto ldgA = [&](int c) {
        const float* src = &h[(size_t)(m0 + ld_row) * K_DIM + c * KC + ld_kh * 16];
        pf[0] = *reinterpret_cast<const float4*>(src);
        pf[1] = *reinterpret_cast<const float4*>(src + 4);
        pf[2] = *reinterpret_cast<const float4*>(src + 8);
        pf[3] = *reinterpret_cast<const float4*>(src + 12);
    };
    auto stsA = [&](int s) {
        uint32_t hp[8], lp[8];
        split_pack(pf[0].x, pf[0].y, hp[0], lp[0]);
        split_pack(pf[0].z, pf[0].w, hp[1], lp[1]);
        split_pack(pf[1].x, pf[1].y, hp[2], lp[2]);
        split_pack(pf[1].z, pf[1].w, hp[3], lp[3]);
        split_pack(pf[2].x, pf[2].y, hp[4], lp[4]);
        split_pack(pf[2].z, pf[2].w, hp[5], lp[5]);
        split_pack(pf[3].x, pf[3].y, hp[6], lp[6]);
        split_pack(pf[3].z, pf[3].w, hp[7], lp[7]);
        uint32_t dst = smem_b + (uint32_t)(s * STAGE_B + ld_row * RSTRIDE + ld_kh * 32);
        sts128(dst,          hp[0], hp[1], hp[2], hp[3]);
        sts128(dst + 16,     hp[4], hp[5], hp[6], hp[7]);
        sts128(dst + PLANE,      lp[0], lp[1], lp[2], lp[3]);
        sts128(dst + PLANE + 16, lp[4], lp[5], lp[6], lp[7]);
    };
    auto cpB = [&](int c, int s) {
        uint32_t dst = smem_b + (uint32_t)(s * STAGE_B + 2 * PLANE +
                                           ld_row * RSTRIDE + ld_kh * 32);
        const uint32_t* sh = &g_Bh[(n0 + ld_row) * 128 + c * 16 + ld_kh * 8];
        const uint32_t* sl = &g_Bl[(n0 + ld_row) * 128 + c * 16 + ld_kh * 8];
        cp16(dst,              sh);
        cp16(dst + 16,         sh + 4);
        cp16(dst + PLANE,      sl);
        cp16(dst + PLANE + 16, sl + 4);
        asm volatile("cp.async.commit_group;" ::: "memory");
    };

    // prologue: fill stage 0
    ldgA(0);
    stsA(0);
    cpB(0, 0);

    for (int c = 0; c < NCHUNK; ++c) {
        const int s = c & 1;
        asm volatile("cp.async.wait_group 0;" ::: "memory");
        __syncthreads();   // stage s ready; stage s^1 free

        if (c + 1 < NCHUNK) {
            cpB(c + 1, s ^ 1);
            ldgA(c + 1);
        }

        const uint32_t abase = smem_b + (uint32_t)(s * STAGE_B);
        const uint32_t bbase = abase + 2 * PLANE;

        #pragma unroll
        for (int kg = 0; kg < 2; ++kg) {
            const uint32_t ka = abase + kg * 32 + a_lane;
            const uint32_t kb = bbase + kg * 32 + b_lane;

            uint4 Ah[2], Al[2], Bh[4], Bl[4];
            Ah[0] = ldsm4(ka);
            Ah[1] = ldsm4(ka + 16 * RSTRIDE);
            #pragma unroll
            for (int p = 0; p < 4; ++p)
                Bh[p] = ldsm4(kb + (uint32_t)(p * 16 * RSTRIDE));

            // term 1: Ah * Bh over all 16 acc tiles (reuse distance 16)
            #pragma unroll
            for (int p = 0; p < 4; ++p)
                #pragma unroll
                for (int mt = 0; mt < 2; ++mt) {
                    mma_bf16(acc[mt][p * 2],     Ah[mt].x, Ah[mt].y, Ah[mt].z, Ah[mt].w,
                             Bh[p].x, Bh[p].y);
                    mma_bf16(acc[mt][p * 2 + 1], Ah[mt].x, Ah[mt].y, Ah[mt].z, Ah[mt].w,
                             Bh[p].z, Bh[p].w);
                }

            // B-lo loads under term-1 retirement
            #pragma unroll
            for (int p = 0; p < 4; ++p)
                Bl[p] = ldsm4(kb + (uint32_t)(p * 16 * RSTRIDE) + PLANE);

            // term 2: Ah * Bl
            #pragma unroll
            for (int p = 0; p < 4; ++p)
                #pragma unroll
                for (int mt = 0; mt < 2; ++mt) {
                    mma_bf16(acc[mt][p * 2],     Ah[mt].x, Ah[mt].y, Ah[mt].z, Ah[mt].w,
                             Bl[p].x, Bl[p].y);
                    mma_bf16(acc[mt][p * 2 + 1], Ah[mt].x, Ah[mt].y, Ah[mt].z, Ah[mt].w,
                             Bl[p].z, Bl[p].w);
                }

            // A-lo loads under term-2 retirement
            Al[0] = ldsm4(ka + PLANE);
            Al[1] = ldsm4(ka + 16 * RSTRIDE + PLANE);

            // term 3: Al * Bh
            #pragma unroll
            for (int p = 0; p < 4; ++p)
                #pragma unroll
                for (int mt = 0; mt < 2; ++mt) {
                    mma_bf16(acc[mt][p * 2],     Al[mt].x, Al[mt].y, Al[mt].z, Al[mt].w,
                             Bh[p].x, Bh[p].y);
                    mma_bf16(acc[mt][p * 2 + 1], Al[mt].x, Al[mt].y, Al[mt].z, Al[mt].w,
                             Bh[p].z, Bh[p].w);
                }
        }

        if (c + 1 < NCHUNK)
            stsA(s ^ 1);
    }

    // ---- epilogue: out = a*acc + (1-a)*h ----
    float a = res_alpha[0];
    a = fminf(fmaxf(a, 0.0f), 1.0f);
    const float ra = 1.0f - a;

    #pragma unroll
    for (int mt = 0; mt < 2; ++mt) {
        const int r0 = m0 + wm + mt * 16 + grp;
        #pragma unroll
        for (int nt = 0; nt < 8; ++nt) {
            const int cc = n0 + wn + nt * 8 + 2 * tig;
            {
                size_t gi = (size_t)r0 * NDIM + cc;
                float2 hv = *reinterpret_cast<const float2*>(&h[gi]);
                float2 o;
                o.x = fmaf(a, acc[mt][nt][0], ra * hv.x);
                o.y = fmaf(a, acc[mt][nt][1], ra * hv.y);
                *reinterpret_cast<float2*>(&out[gi]) = o;
            }
            {
                size_t gi = (size_t)(r0 + 8) * NDIM + cc;
                float2 hv = *reinterpret_cast<const float2*>(&h[gi]);
                float2 o;
                o.x = fmaf(a, acc[mt][nt][2], ra * hv.x);
                o.y = fmaf(a, acc[mt][nt][3], ra * hv.y);
                *reinterpret_cast<float2*>(&out[gi]) = o;
            }
        }
    }
}

extern "C" void kernel_launch(void* const* d_in, const int* in_sizes, int n_in,
                              void* d_out, int out_size) {
    const float* h         = (const float*)d_in[0];   // [8, 2048, 256]
    // d_in[1] = adj (unused)
    const float* W         = (const float*)d_in[2];   // [4, 256, 64]
    const float* res_alpha = (const float*)d_in[3];
    float* out             = (float*)d_out;

    const int M = in_sizes[0] / K_DIM;                // 16384

    prep_Bt<<<(NDIM * K_DIM / 2) / 256, 256>>>(W);

    const int smem_bytes = 2 * STAGE_B;               // 81920
    cudaFuncSetAttribute(gat_mma_gemm,
                         cudaFuncAttributeMaxDynamicSharedMemorySize, smem_bytes);
    dim3 grid(NDIM / BN, M / BM);                     // (2, 128)
    gat_mma_gemm<<<grid, THREADS, smem_bytes>>>(h, res_alpha, out);
}

// round 17
// speedup vs baseline: 1.2653x; 1.2653x over previous
#include <cuda_runtime.h>
#include <cuda_fp16.h>
#include <cstdint>

// out[m,n] = a * (h[m,:] @ B2[:,n]) + (1-a) * h[m,n]
// B2[k, head*64+d] = W[head,k,d]; a = clip(res_alpha,0,1).
// (softmax row-sums are exactly 1 -> attention block is identity; adj unused)
//
// R17: fp16 2-term emulated-fp32 GEMM on mma.m16n8k16.f32.f16.f16.f32:
//   A = Ahi + Alo (fp16 RN split, repr err ~2^-22), Br = fp16_rn(B)
//   D = Ahi*Br + Alo*Br     (error ~2^-11/sqrt(3) from B rounding only)
// MMA count 1.57M -> 1.05M vs the 3-term bf16 kernel; the per-warp MMA
// issue interval proved to be the invariant binder across R10-R16, and
// time has tracked MMA count (R7). B is one smem plane (traffic halves).

#define K_DIM   256
#define NDIM    256
#define BM      128
#define BN      128
#define KC      32
#define NCHUNK  (K_DIM / KC)
#define RSTRIDE 80                       // bytes per smem row (64 data + 16 pad)
#define PLANE   (128 * RSTRIDE)          // 10240 B per plane (128 rows)
#define STAGE_B (3 * PLANE)              // Ahi, Alo, Br = 30720 B
#define THREADS 256

__device__ uint32_t g_Br[NDIM * K_DIM / 2];   // [n][pair] fp16x2 of W^T

// pack two fp32 -> fp16x2 RN (hi) + fp16x2 residual (lo)
__device__ __forceinline__ void split_pack_f16(float f0, float f1,
                                               uint32_t& hi, uint32_t& lo) {
    __half h0 = __float2half_rn(f0);
    __half h1 = __float2half_rn(f1);
    float r0 = f0 - __half2float(h0);
    float r1 = f1 - __half2float(h1);
    __half2 H = __halves2half2(h0, h1);
    __half2 L = __halves2half2(__float2half_rn(r0), __float2half_rn(r1));
    hi = *reinterpret_cast<uint32_t*>(&H);
    lo = *reinterpret_cast<uint32_t*>(&L);
}

__global__ void prep_Bt(const float* __restrict__ W) {
    int idx = blockIdx.x * blockDim.x + threadIdx.x;   // 32768
    int n = idx >> 7;
    int p = idx & 127;
    int head = n >> 6, d = n & 63;
    float f0 = W[((size_t)head * K_DIM + 2 * p) * 64 + d];
    float f1 = W[((size_t)head * K_DIM + 2 * p + 1) * 64 + d];
    __half2 H = __halves2half2(__float2half_rn(f0), __float2half_rn(f1));
    g_Br[n * 128 + p] = *reinterpret_cast<uint32_t*>(&H);
}

__device__ __forceinline__ void mma_f16(float d[4],
                                        uint32_t a0, uint32_t a1, uint32_t a2, uint32_t a3,
                                        uint32_t b0, uint32_t b1) {
    asm volatile(
        "mma.sync.aligned.m16n8k16.row.col.f32.f16.f16.f32 "
        "{%0,%1,%2,%3}, {%4,%5,%6,%7}, {%8,%9}, {%0,%1,%2,%3};"
        : "+f"(d[0]), "+f"(d[1]), "+f"(d[2]), "+f"(d[3])
        : "r"(a0), "r"(a1), "r"(a2), "r"(a3), "r"(b0), "r"(b1));
}
__device__ __forceinline__ uint4 ldsm4(uint32_t saddr) {
    uint4 v;
    asm volatile("ldmatrix.sync.aligned.m8n8.x4.shared.b16 {%0,%1,%2,%3}, [%4];"
                 : "=r"(v.x), "=r"(v.y), "=r"(v.z), "=r"(v.w) : "r"(saddr));
    return v;
}
__device__ __forceinline__ void cp16(uint32_t saddr, const void* g) {
    asm volatile("cp.async.cg.shared.global [%0], [%1], 16;"
                 :: "r"(saddr), "l"(g) : "memory");
}
__device__ __forceinline__ void sts128(uint32_t saddr, uint32_t x, uint32_t y,
                                       uint32_t z, uint32_t w) {
    asm volatile("st.shared.v4.u32 [%0], {%1,%2,%3,%4};"
                 :: "r"(saddr), "r"(x), "r"(y), "r"(z), "r"(w) : "memory");
}

__global__ __launch_bounds__(THREADS, 2)
void gat_mma_gemm(const float* __restrict__ h,
                  const float* __restrict__ res_alpha,
                  float* __restrict__ out)
{
    extern __shared__ uint32_t su[];
    const uint32_t smem_b = (uint32_t)__cvta_generic_to_shared(su);

    const int tid = threadIdx.x;
    const int wid = tid >> 5;
    const int lid = tid & 31;
    const int grp = lid >> 2;
    const int tig = lid & 3;

    const int m0 = blockIdx.y * BM;
    const int n0 = blockIdx.x * BN;
    const int wm = (wid & 3) * 32;
    const int wn = (wid >> 2) * 64;

    const uint32_t a_lane = (uint32_t)((wm + (lid & 15)) * RSTRIDE + ((lid >> 4) & 1) * 16);
    const uint32_t b_lane = (uint32_t)((wn + (lid & 7) + ((lid >> 4) & 1) * 8) * RSTRIDE +
                                      ((lid >> 3) & 1) * 16);

    const int ld_row = tid >> 1;
    const int ld_kh  = tid & 1;

    float acc[2][8][4];
    #pragma unroll
    for (int mt = 0; mt < 2; ++mt)
        #pragma unroll
        for (int nt = 0; nt < 8; ++nt)
            #pragma unroll
            for (int q = 0; q < 4; ++q)
                acc[mt][nt][q] = 0.0f;

    float4 pf[4];

    auto ldgA = [&](int c) {
        const float* src = &h[(size_t)(m0 + ld_row) * K_DIM + c * KC + ld_kh * 16];
        pf[0] = *reinterpret_cast<const float4*>(src);
        pf[1] = *reinterpret_cast<const float4*>(src + 4);
        pf[2] = *reinterpret_cast<const float4*>(src + 8);
        pf[3] = *reinterpret_cast<const float4*>(src + 12);
    };
    auto stsA = [&](int s) {
        uint32_t hp[8], lp[8];
        split_pack_f16(pf[0].x, pf[0].y, hp[0], lp[0]);
        split_pack_f16(pf[0].z, pf[0].w, hp[1], lp[1]);
        split_pack_f16(pf[1].x, pf[1].y, hp[2], lp[2]);
        split_pack_f16(pf[1].z, pf[1].w, hp[3], lp[3]);
        split_pack_f16(pf[2].x, pf[2].y, hp[4], lp[4]);
        split_pack_f16(pf[2].z, pf[2].w, hp[5], lp[5]);
        split_pack_f16(pf[3].x, pf[3].y, hp[6], lp[6]);
        split_pack_f16(pf[3].z, pf[3].w, hp[7], lp[7]);
        uint32_t dst = smem_b + (uint32_t)(s * STAGE_B + ld_row * RSTRIDE + ld_kh * 32);
        sts128(dst,              hp[0], hp[1], hp[2], hp[3]);
        sts128(dst + 16,         hp[4], hp[5], hp[6], hp[7]);
        sts128(dst + PLANE,      lp[0], lp[1], lp[2], lp[3]);
        sts128(dst + PLANE + 16, lp[4], lp[5], lp[6], lp[7]);
    };
    auto cpB = [&](int c, int s) {
        uint32_t dst = smem_b + (uint32_t)(s * STAGE_B + 2 * PLANE +
                                           ld_row * RSTRIDE + ld_kh * 32);
        const uint32_t* sb = &g_Br[(n0 + ld_row) * 128 + c * 16 + ld_kh * 8];
        cp16(dst,      sb);
        cp16(dst + 16, sb + 4);
        asm volatile("cp.async.commit_group;" ::: "memory");
    };

    // prologue: fill stage 0
    ldgA(0);
    stsA(0);
    cpB(0, 0);

    for (int c = 0; c < NCHUNK; ++c) {
        const int s = c & 1;
        asm volatile("cp.async.wait_group 0;" ::: "memory");
        __syncthreads();   // stage s ready; stage s^1 free

        if (c + 1 < NCHUNK) {
            cpB(c + 1, s ^ 1);
            ldgA(c + 1);
        }

        const uint32_t abase = smem_b + (uint32_t)(s * STAGE_B);
        const uint32_t bbase = abase + 2 * PLANE;

        #pragma unroll
        for (int kg = 0; kg < 2; ++kg) {
            const uint32_t ka = abase + kg * 32 + a_lane;
            const uint32_t kb = bbase + kg * 32 + b_lane;

            uint4 Ah[2], Al[2], Bf[4];
            Ah[0] = ldsm4(ka);
            Ah[1] = ldsm4(ka + 16 * RSTRIDE);
            #pragma unroll
            for (int p = 0; p < 4; ++p)
                Bf[p] = ldsm4(kb + (uint32_t)(p * 16 * RSTRIDE));

            // term 1: Ahi * Br over all 16 acc tiles (reuse distance 16)
            #pragma unroll
            for (int p = 0; p < 4; ++p)
                #pragma unroll
                for (int mt = 0; mt < 2; ++mt) {
                    mma_f16(acc[mt][p * 2],     Ah[mt].x, Ah[mt].y, Ah[mt].z, Ah[mt].w,
                            Bf[p].x, Bf[p].y);
                    mma_f16(acc[mt][p * 2 + 1], Ah[mt].x, Ah[mt].y, Ah[mt].z, Ah[mt].w,
                            Bf[p].z, Bf[p].w);
                }

            // A-lo loads issued under term-1 retirement
            Al[0] = ldsm4(ka + PLANE);
            Al[1] = ldsm4(ka + 16 * RSTRIDE + PLANE);

            // term 2: Alo * Br
            #pragma unroll
            for (int p = 0; p < 4; ++p)
                #pragma unroll
                for (int mt = 0; mt < 2; ++mt) {
                    mma_f16(acc[mt][p * 2],     Al[mt].x, Al[mt].y, Al[mt].z, Al[mt].w,
                            Bf[p].x, Bf[p].y);
                    mma_f16(acc[mt][p * 2 + 1], Al[mt].x, Al[mt].y, Al[mt].z, Al[mt].w,
                            Bf[p].z, Bf[p].w);
                }
        }

        if (c + 1 < NCHUNK)
            stsA(s ^ 1);
    }

    // ---- epilogue: out = a*acc + (1-a)*h ----
    float a = res_alpha[0];
    a = fminf(fmaxf(a, 0.0f), 1.0f);
    const float ra = 1.0f - a;

    #pragma unroll
    for (int mt = 0; mt < 2; ++mt) {
        const int r0 = m0 + wm + mt * 16 + grp;
        #pragma unroll
        for (int nt = 0; nt < 8; ++nt) {
            const int cc = n0 + wn + nt * 8 + 2 * tig;
            {
                size_t gi = (size_t)r0 * NDIM + cc;
                float2 hv = *reinterpret_cast<const float2*>(&h[gi]);
                float2 o;
                o.x = fmaf(a, acc[mt][nt][0], ra * hv.x);
                o.y = fmaf(a, acc[mt][nt][1], ra * hv.y);
                *reinterpret_cast<float2*>(&out[gi]) = o;
            }
            {
                size_t gi = (size_t)(r0 + 8) * NDIM + cc;
                float2 hv = *reinterpret_cast<const float2*>(&h[gi]);
                float2 o;
                o.x = fmaf(a, acc[mt][nt][2], ra * hv.x);
                o.y = fmaf(a, acc[mt][nt][3], ra * hv.y);
                *reinterpret_cast<float2*>(&out[gi]) = o;
            }
        }
    }
}

extern "C" void kernel_launch(void* const* d_in, const int* in_sizes, int n_in,
                              void* d_out, int out_size) {
    const float* h         = (const float*)d_in[0];   // [8, 2048, 256]
    // d_in[1] = adj (unused)
    const float* W         = (const float*)d_in[2];   // [4, 256, 64]
    const float* res_alpha = (const float*)d_in[3];
    float* out             = (float*)d_out;

    const int M = in_sizes[0] / K_DIM;                // 16384

    prep_Bt<<<(NDIM * K_DIM / 2) / 256, 256>>>(W);

    const int smem_bytes = 2 * STAGE_B;               // 61440
    cudaFuncSetAttribute(gat_mma_gemm,
                         cudaFuncAttributeMaxDynamicSharedMemorySize, smem_bytes);
    dim3 grid(NDIM / BN, M / BM);                     // (2, 128)
    gat_mma_gemm<<<grid, THREADS, smem_bytes>>>(h, res_alpha, out);
}